// round 3
// baseline (speedup 1.0000x reference)
#include <cuda_runtime.h>
#include <math.h>

#define B_      16
#define CIN_    256
#define COUT_   256
#define HW_     64
#define KN_     4
#define PI_F    3.14159265358979323846f
#define BN_EPS_ 1e-5f

// ---------------- scratch (static __device__, no allocation) ----------------
__device__ float g_pooled[B_ * CIN_];                    // [b][c]
__device__ float g_T[B_ * 9 * 36];                       // [b][p][n*9+q], lambda folded in
__device__ float g_rw[(size_t)B_ * CIN_ * COUT_ * 9];    // [b][ci][co][k]  (37.7 MB)

// ---------------- packed f32x2 helpers ----------------
__device__ __forceinline__ unsigned long long pk2(float lo, float hi) {
    unsigned long long d;
    asm("mov.b64 %0, {%1,%2};" : "=l"(d) : "f"(lo), "f"(hi));
    return d;
}
__device__ __forceinline__ void fma2(unsigned long long& d, unsigned long long a, unsigned long long b) {
    asm("fma.rn.f32x2 %0, %1, %2, %0;" : "+l"(d) : "l"(a), "l"(b));
}
__device__ __forceinline__ float2 upk2(unsigned long long d) {
    float2 f;
    asm("mov.b64 {%0,%1}, %2;" : "=f"(f.x), "=f"(f.y) : "l"(d));
    return f;
}

// ---------------- kernel 1: global average pool ----------------
__global__ void pool_kernel(const float* __restrict__ x) {
    int blk = blockIdx.x;                       // b*CIN + c
    const float* p = x + (size_t)blk * (HW_ * HW_);
    float s = 0.f;
    for (int i = threadIdx.x; i < HW_ * HW_; i += 256) s += p[i];
    #pragma unroll
    for (int o = 16; o; o >>= 1) s += __shfl_xor_sync(0xffffffffu, s, o);
    __shared__ float red[8];
    if ((threadIdx.x & 31) == 0) red[threadIdx.x >> 5] = s;
    __syncthreads();
    if (threadIdx.x == 0) {
        float t = 0.f;
        #pragma unroll
        for (int i = 0; i < 8; i++) t += red[i];
        g_pooled[blk] = t * (1.f / (HW_ * HW_));
    }
}

// ---------------- kernel 2: routing heads + rotation matrices -> g_T ----------------
__global__ void route_kernel(const float* __restrict__ wl, const float* __restrict__ wt) {
    int t = threadIdx.x;
    if (t >= B_ * KN_) return;
    int b = t >> 2, n = t & 3;
    const float* p = g_pooled + b * CIN_;
    float dl = 0.f, dt = 0.f;
    for (int c = 0; c < CIN_; c++) {
        float pc = p[c];
        dl += pc * wl[c * KN_ + n];
        dt += pc * wt[c * KN_ + n];
    }
    float lam = 1.f / (1.f + expf(-dl));
    float th  = (dt / (1.f + fabsf(dt))) * PI_F;

    float xc = cosf(th), ys = sinf(th);
    float a = xc - ys, bxy = xc * ys, cc = xc + ys;

    float R[81];
    #pragma unroll
    for (int i = 0; i < 81; i++) R[i] = 0.f;

    if (th >= 0.f) {
        R[0]  = a;          R[1]  = 1.f - a;
        R[10] = xc - bxy;   R[11] = bxy;        R[13] = 1.f - cc + bxy; R[14] = ys - bxy;
        R[20] = a;          R[23] = 1.f - a;
        R[27] = bxy;        R[28] = ys - bxy;   R[30] = xc - bxy;       R[31] = 1.f - cc + bxy;
        R[40] = 1.f;
        R[49] = 1.f - cc + bxy; R[50] = xc - bxy; R[52] = ys - bxy;     R[53] = bxy;
        R[57] = 1.f - a;    R[60] = a;
        R[66] = ys - bxy;   R[67] = 1.f - cc + bxy; R[69] = bxy;        R[70] = xc - bxy;
        R[79] = 1.f - a;    R[80] = a;
    } else {
        R[0]  = cc;         R[3]  = 1.f - cc;
        R[9]  = -bxy;       R[10] = xc + bxy;   R[12] = bxy - ys;       R[13] = 1.f - a - bxy;
        R[19] = 1.f - cc;   R[20] = cc;
        R[30] = xc + bxy;   R[31] = 1.f - a - bxy; R[33] = -bxy;        R[34] = bxy - ys;
        R[40] = 1.f;
        R[46] = bxy - ys;   R[47] = -bxy;       R[49] = 1.f - a - bxy;  R[50] = xc + bxy;
        R[60] = cc;         R[61] = 1.f - cc;
        R[67] = 1.f - a - bxy; R[68] = bxy - ys; R[70] = xc + bxy;      R[71] = -bxy;
        R[77] = 1.f - cc;   R[80] = cc;
    }

    #pragma unroll
    for (int pp = 0; pp < 9; pp++)
        #pragma unroll
        for (int q = 0; q < 9; q++)
            g_T[b * 324 + pp * 36 + n * 9 + q] = lam * R[pp * 9 + q];
}

// ---------------- kernel 3: rotated weights -> g_rw[b][ci][co][k] ----------------
__global__ void rotw_kernel(const float* __restrict__ weight) {
    int ci = blockIdx.x;
    int b  = blockIdx.y;
    int co = threadIdx.x;

    __shared__ float T[324];
    for (int i = threadIdx.x; i < 324; i += 256) T[i] = g_T[b * 324 + i];
    __syncthreads();

    float wv[36];
    #pragma unroll
    for (int n = 0; n < KN_; n++) {
        const float* wp = weight + ((size_t)(n * COUT_ + co) * CIN_ + ci) * 9;
        #pragma unroll
        for (int q = 0; q < 9; q++) wv[n * 9 + q] = wp[q];
    }

    float* outp = g_rw + ((size_t)(b * CIN_ + ci) * COUT_ + co) * 9;
    #pragma unroll
    for (int p = 0; p < 9; p++) {
        float s = 0.f;
        #pragma unroll
        for (int m = 0; m < 36; m++) s += T[p * 36 + m] * wv[m];
        outp[p] = s;
    }
}

// ---------------- kernel 4: grouped 3x3 conv + BN + ReLU ----------------
// grid: (16 spatial tiles, 4 cout-groups of 64, 16 batches); block: 256 threads
// thread = 8 cout x 8 pixels (one row segment), f32x2 packed accumulators.
#define CIK 8
__global__ __launch_bounds__(256, 2)
void conv_kernel(const float* __restrict__ x,
                 const float* __restrict__ bn_gamma, const float* __restrict__ bn_beta,
                 const float* __restrict__ bn_mean,  const float* __restrict__ bn_var,
                 float* __restrict__ out) {
    int b    = blockIdx.z;
    int cog  = blockIdx.y;
    int tile = blockIdx.x;
    int h0 = (tile >> 2) * 16;
    int w0 = (tile & 3) * 16;

    int tid   = threadIdx.x;
    int tco   = tid >> 5;        // 0..7 -> 8-cout group
    int lane  = tid & 31;
    int r     = lane >> 1;       // row 0..15 within tile
    int cside = lane & 1;        // col half (0 or 8)

    __shared__ __align__(16) float xs[CIK * 18 * 20];   // [ci][18 rows][20 stride]
    __shared__ float wsm[CIK * 64 * 9];                 // [ci][co(64)][9]

    unsigned long long acc[8][4];
    #pragma unroll
    for (int i = 0; i < 8; i++)
        #pragma unroll
        for (int j = 0; j < 4; j++) acc[i][j] = 0ull;

    for (int ci0 = 0; ci0 < CIN_; ci0 += CIK) {
        __syncthreads();
        // stage x tile with halo (18x18 valid, stride 20)
        const float* xb = x + ((size_t)b * CIN_ + ci0) * (HW_ * HW_);
        for (int e = tid; e < CIK * 18 * 18; e += 256) {
            int ci  = e / 324;
            int rem = e - ci * 324;
            int i   = rem / 18;
            int j   = rem - i * 18;
            int gh = h0 - 1 + i, gw = w0 - 1 + j;
            float v = 0.f;
            if ((unsigned)gh < (unsigned)HW_ && (unsigned)gw < (unsigned)HW_)
                v = xb[ci * (HW_ * HW_) + gh * HW_ + gw];
            xs[ci * 360 + i * 20 + j] = v;
        }
        // stage weights (contiguous: [ci][co within group][9])
        const float* wb = g_rw + ((size_t)(b * CIN_ + ci0) * COUT_ + cog * 64) * 9;
        for (int e = tid; e < CIK * 576; e += 256) {
            int ci  = e / 576;
            int rem = e - ci * 576;
            wsm[e] = wb[(size_t)ci * COUT_ * 9 + rem];
        }
        __syncthreads();

        #pragma unroll
        for (int ci = 0; ci < CIK; ci++) {
            const float* wrow  = &wsm[ci * 576 + tco * 72];       // 8 co x 9 (warp-broadcast)
            const float* xbase = &xs[ci * 360 + cside * 8];
            #pragma unroll
            for (int kh = 0; kh < 3; kh++) {
                const float* xp = xbase + (r + kh) * 20;
                float xr[10];
                float4 v0 = *(const float4*)xp;
                float4 v1 = *(const float4*)(xp + 4);
                float2 v2 = *(const float2*)(xp + 8);
                xr[0] = v0.x; xr[1] = v0.y; xr[2] = v0.z; xr[3] = v0.w;
                xr[4] = v1.x; xr[5] = v1.y; xr[6] = v1.z; xr[7] = v1.w;
                xr[8] = v2.x; xr[9] = v2.y;
                #pragma unroll
                for (int kw = 0; kw < 3; kw++) {
                    unsigned long long xp0 = pk2(xr[kw + 0], xr[kw + 1]);
                    unsigned long long xp1 = pk2(xr[kw + 2], xr[kw + 3]);
                    unsigned long long xp2 = pk2(xr[kw + 4], xr[kw + 5]);
                    unsigned long long xp3 = pk2(xr[kw + 6], xr[kw + 7]);
                    #pragma unroll
                    for (int ico = 0; ico < 8; ico++) {
                        float w = wrow[ico * 9 + kh * 3 + kw];
                        unsigned long long wp = pk2(w, w);
                        fma2(acc[ico][0], wp, xp0);
                        fma2(acc[ico][1], wp, xp1);
                        fma2(acc[ico][2], wp, xp2);
                        fma2(acc[ico][3], wp, xp3);
                    }
                }
            }
        }
    }

    // epilogue: BN (inference) + ReLU, vectorized store
    int hrow = h0 + r;
    int wcol = w0 + cside * 8;
    #pragma unroll
    for (int ico = 0; ico < 8; ico++) {
        int co = cog * 64 + tco * 8 + ico;
        float s  = bn_gamma[co] * rsqrtf(bn_var[co] + BN_EPS_);
        float bb = bn_beta[co] - bn_mean[co] * s;
        float o[8];
        #pragma unroll
        for (int j = 0; j < 4; j++) {
            float2 v = upk2(acc[ico][j]);
            o[2 * j + 0] = fmaxf(v.x * s + bb, 0.f);
            o[2 * j + 1] = fmaxf(v.y * s + bb, 0.f);
        }
        float* op = out + ((size_t)(b * COUT_ + co) * HW_ + hrow) * HW_ + wcol;
        float4 s0 = make_float4(o[0], o[1], o[2], o[3]);
        float4 s1 = make_float4(o[4], o[5], o[6], o[7]);
        *(float4*)op       = s0;
        *(float4*)(op + 4) = s1;
    }
}

// ---------------- launcher ----------------
extern "C" void kernel_launch(void* const* d_in, const int* in_sizes, int n_in,
                              void* d_out, int out_size) {
    const float* x        = (const float*)d_in[0];
    const float* weight   = (const float*)d_in[1];
    const float* w_lambda = (const float*)d_in[2];
    const float* w_theta  = (const float*)d_in[3];
    const float* bn_gamma = (const float*)d_in[4];
    const float* bn_beta  = (const float*)d_in[5];
    const float* bn_mean  = (const float*)d_in[6];
    const float* bn_var   = (const float*)d_in[7];
    float* out = (float*)d_out;

    pool_kernel<<<B_ * CIN_, 256>>>(x);
    route_kernel<<<1, 64>>>(w_lambda, w_theta);
    rotw_kernel<<<dim3(CIN_, B_), 256>>>(weight);
    conv_kernel<<<dim3(16, 4, B_), 256>>>(x, bn_gamma, bn_beta, bn_mean, bn_var, out);
}

// round 5
// speedup vs baseline: 2.7600x; 2.7600x over previous
#include <cuda_runtime.h>
#include <cuda_bf16.h>
#include <math.h>
#include <stdint.h>

#define B_      16
#define CIN_    256
#define COUT_   256
#define HW_     64
#define KN_     4
#define PI_F    3.14159265358979323846f
#define BN_EPS_ 1e-5f

#define PADW    66
#define PROWS   (PADW * PADW)

// ---------------- scratch (static __device__, no allocation) ----------------
__device__ float g_pooled[B_ * CIN_];
__device__ float g_T[B_ * 9 * 36];
__device__ __nv_bfloat16 g_wh[(size_t)B_ * 9 * COUT_ * CIN_];   // [b][k][co][ci] hi
__device__ __nv_bfloat16 g_wl[(size_t)B_ * 9 * COUT_ * CIN_];   // lo
__device__ __nv_bfloat16 g_xh[(size_t)B_ * PROWS * CIN_];       // [b][padded px][ci] hi
__device__ __nv_bfloat16 g_xl[(size_t)B_ * PROWS * CIN_];       // lo

// ---------------- helpers ----------------
__device__ __forceinline__ uint32_t smem_u32(const void* p) {
    uint32_t a;
    asm("{ .reg .u64 t; cvta.to.shared.u64 t, %1; cvt.u32.u64 %0, t; }" : "=r"(a) : "l"(p));
    return a;
}
#define SWZ128(o) ((o) ^ (((o) >> 3) & 0x70))

#define CP_ASYNC16(dst, src) asm volatile("cp.async.cg.shared.global [%0], [%1], 16;" :: "r"(dst), "l"(src) : "memory")
#define CP_COMMIT()          asm volatile("cp.async.commit_group;" ::: "memory")

#define LDSM_X4(r, a)                                                                     \
    asm volatile("ldmatrix.sync.aligned.m8n8.x4.shared.b16 {%0,%1,%2,%3}, [%4];"          \
                 : "=r"((r)[0]), "=r"((r)[1]), "=r"((r)[2]), "=r"((r)[3]) : "r"(a))

#define MMA_BF16(d, a, b0, b1)                                                            \
    asm volatile("mma.sync.aligned.m16n8k16.row.col.f32.bf16.bf16.f32 "                   \
                 "{%0,%1,%2,%3},{%4,%5,%6,%7},{%8,%9},{%0,%1,%2,%3};"                     \
                 : "+f"((d)[0]), "+f"((d)[1]), "+f"((d)[2]), "+f"((d)[3])                 \
                 : "r"((a)[0]), "r"((a)[1]), "r"((a)[2]), "r"((a)[3]), "r"(b0), "r"(b1))

// ---------------- kernel 1: global average pool ----------------
__global__ void pool_kernel(const float* __restrict__ x) {
    int blk = blockIdx.x;
    const float* p = x + (size_t)blk * (HW_ * HW_);
    float s = 0.f;
    for (int i = threadIdx.x; i < HW_ * HW_; i += 256) s += p[i];
    #pragma unroll
    for (int o = 16; o; o >>= 1) s += __shfl_xor_sync(0xffffffffu, s, o);
    __shared__ float red[8];
    if ((threadIdx.x & 31) == 0) red[threadIdx.x >> 5] = s;
    __syncthreads();
    if (threadIdx.x == 0) {
        float t = 0.f;
        #pragma unroll
        for (int i = 0; i < 8; i++) t += red[i];
        g_pooled[blk] = t * (1.f / (HW_ * HW_));
    }
}

// ---------------- kernel 2: routing heads + rotation matrices -> g_T ----------------
__global__ void route_kernel(const float* __restrict__ wl, const float* __restrict__ wt) {
    int t = threadIdx.x;
    if (t >= B_ * KN_) return;
    int b = t >> 2, n = t & 3;
    const float* p = g_pooled + b * CIN_;
    float dl = 0.f, dt = 0.f;
    for (int c = 0; c < CIN_; c++) {
        float pc = p[c];
        dl += pc * wl[c * KN_ + n];
        dt += pc * wt[c * KN_ + n];
    }
    float lam = 1.f / (1.f + expf(-dl));
    float th  = (dt / (1.f + fabsf(dt))) * PI_F;

    float xc = cosf(th), ys = sinf(th);
    float a = xc - ys, bxy = xc * ys, cc = xc + ys;

    float R[81];
    #pragma unroll
    for (int i = 0; i < 81; i++) R[i] = 0.f;

    if (th >= 0.f) {
        R[0]  = a;          R[1]  = 1.f - a;
        R[10] = xc - bxy;   R[11] = bxy;        R[13] = 1.f - cc + bxy; R[14] = ys - bxy;
        R[20] = a;          R[23] = 1.f - a;
        R[27] = bxy;        R[28] = ys - bxy;   R[30] = xc - bxy;       R[31] = 1.f - cc + bxy;
        R[40] = 1.f;
        R[49] = 1.f - cc + bxy; R[50] = xc - bxy; R[52] = ys - bxy;     R[53] = bxy;
        R[57] = 1.f - a;    R[60] = a;
        R[66] = ys - bxy;   R[67] = 1.f - cc + bxy; R[69] = bxy;        R[70] = xc - bxy;
        R[79] = 1.f - a;    R[80] = a;
    } else {
        R[0]  = cc;         R[3]  = 1.f - cc;
        R[9]  = -bxy;       R[10] = xc + bxy;   R[12] = bxy - ys;       R[13] = 1.f - a - bxy;
        R[19] = 1.f - cc;   R[20] = cc;
        R[30] = xc + bxy;   R[31] = 1.f - a - bxy; R[33] = -bxy;        R[34] = bxy - ys;
        R[40] = 1.f;
        R[46] = bxy - ys;   R[47] = -bxy;       R[49] = 1.f - a - bxy;  R[50] = xc + bxy;
        R[60] = cc;         R[61] = 1.f - cc;
        R[67] = 1.f - a - bxy; R[68] = bxy - ys; R[70] = xc + bxy;      R[71] = -bxy;
        R[77] = 1.f - cc;   R[80] = cc;
    }

    #pragma unroll
    for (int pp = 0; pp < 9; pp++)
        #pragma unroll
        for (int q = 0; q < 9; q++)
            g_T[b * 324 + pp * 36 + n * 9 + q] = lam * R[pp * 9 + q];
}

// ---------------- kernel 3: rotated weights -> bf16 hi/lo, layout [b][k][co][ci] ----------------
__global__ void rotw_kernel(const float* __restrict__ weight) {
    int co = blockIdx.x;
    int b  = blockIdx.y;
    int ci = threadIdx.x;

    __shared__ float T[324];
    for (int i = threadIdx.x; i < 324; i += 256) T[i] = g_T[b * 324 + i];
    __syncthreads();

    float wv[36];
    #pragma unroll
    for (int n = 0; n < KN_; n++) {
        const float* wp = weight + ((size_t)((n * COUT_ + co) * CIN_ + ci)) * 9;
        #pragma unroll
        for (int q = 0; q < 9; q++) wv[n * 9 + q] = wp[q];
    }

    #pragma unroll
    for (int p = 0; p < 9; p++) {
        float s = 0.f;
        #pragma unroll
        for (int m = 0; m < 36; m++) s += T[p * 36 + m] * wv[m];
        __nv_bfloat16 hi = __float2bfloat16(s);
        __nv_bfloat16 lo = __float2bfloat16(s - __bfloat162float(hi));
        size_t o = ((size_t)(b * 9 + p) * COUT_ + co) * CIN_ + ci;
        g_wh[o] = hi;
        g_wl[o] = lo;
    }
}

// ---------------- kernel 4: zero padded borders of xT ----------------
__global__ void border_kernel() {
    int pr = blockIdx.x;
    int b  = blockIdx.y;
    int hp = pr / PADW, wp = pr - hp * PADW;
    if (hp != 0 && hp != PADW - 1 && wp != 0 && wp != PADW - 1) return;
    size_t base = ((size_t)b * PROWS + pr) * CIN_;
    int t = threadIdx.x;
    ((uint32_t*)(g_xh + base))[t] = 0u;
    ((uint32_t*)(g_xl + base))[t] = 0u;
}

// ---------------- kernel 5: transpose+convert x -> xT[b][padded px][ci] hi/lo ----------------
__global__ void xpose_kernel(const float* __restrict__ x) {
    int b   = blockIdx.z;
    int ci0 = blockIdx.y * 64;
    int px0 = blockIdx.x * 32;
    __shared__ float t[64][33];
    int tx = threadIdx.x & 31, ty = threadIdx.x >> 5;

    const float* xb = x + ((size_t)(b * CIN_ + ci0)) * (HW_ * HW_) + px0;
    #pragma unroll
    for (int i = 0; i < 8; i++)
        t[ty + 8 * i][tx] = xb[(size_t)(ty + 8 * i) * (HW_ * HW_) + tx];
    __syncthreads();

    #pragma unroll
    for (int i = 0; i < 4; i++) {
        int px = px0 + ty + 8 * i;
        int h = px >> 6, w = px & 63;
        int pr = (h + 1) * PADW + (w + 1);
        size_t base = ((size_t)b * PROWS + pr) * CIN_ + ci0;
        float a0 = t[2 * tx][ty + 8 * i];
        float a1 = t[2 * tx + 1][ty + 8 * i];
        __nv_bfloat16 h0 = __float2bfloat16(a0);
        __nv_bfloat16 h1 = __float2bfloat16(a1);
        __nv_bfloat16 l0 = __float2bfloat16(a0 - __bfloat162float(h0));
        __nv_bfloat16 l1 = __float2bfloat16(a1 - __bfloat162float(h1));
        __nv_bfloat162 vh; vh.x = h0; vh.y = h1;
        __nv_bfloat162 vl; vl.x = l0; vl.y = l1;
        ((__nv_bfloat162*)(g_xh + base))[tx] = vh;
        ((__nv_bfloat162*)(g_xl + base))[tx] = vl;
    }
}

// ---------------- kernel 6: HMMA conv GEMM + BN + ReLU ----------------
// CTA 256 thr = 8 warps (2m x 4n), tile 128 co x 256 px; warp tile 64x64.
// 36 stages (9 taps x 4 ci-chunks of 64), 96KB/stage double-buffered.
#define BUF_BYTES 98304
#define NSTAGE    36

__device__ __forceinline__ void stage_tiles(uint32_t sbase, int b, int cog, int pxg,
                                            int s, int tid) {
    int k   = s >> 2;
    int ci0 = (s & 3) << 6;
    int dh  = k / 3 - 1, dw = k % 3 - 1;
    uint32_t buf = sbase + 1024 + (uint32_t)(s & 1) * BUF_BYTES;

    // A: weights [128 co x 64 ci] hi+lo = 2048 x 16B
    size_t wbase = (((size_t)(b * 9 + k) * COUT_ + cog * 128) * CIN_ + ci0) * 2;
    #pragma unroll
    for (int it = 0; it < 8; it++) {
        int c = tid + it * 256;
        int row = c >> 3, c16 = c & 7;
        int hl = row >> 7, r = row & 127;
        uint32_t dst = buf + (uint32_t)hl * 16384 + SWZ128((uint32_t)(r * 128 + c16 * 16));
        const char* src = (const char*)(hl ? g_wl : g_wh) + wbase + (size_t)r * 512 + c16 * 16;
        CP_ASYNC16(dst, src);
    }
    // B: x rows [256 px x 64 ci] hi+lo = 4096 x 16B
    int hbase = 4 * pxg + dh + 1;
    #pragma unroll
    for (int it = 0; it < 16; it++) {
        int c = tid + it * 256;
        int row = c >> 3, c16 = c & 7;
        int hl = row >> 8, p = row & 255;
        int hh = p >> 6, ww = p & 63;
        int pr = (hbase + hh) * PADW + (ww + dw + 1);
        uint32_t dst = buf + 32768 + (uint32_t)hl * 32768 + SWZ128((uint32_t)(p * 128 + c16 * 16));
        const char* src = (const char*)(hl ? g_xl : g_xh)
                          + (((size_t)b * PROWS + pr) * CIN_ + ci0) * 2 + c16 * 16;
        CP_ASYNC16(dst, src);
    }
}

__global__ void __launch_bounds__(256, 1)
conv_kernel(const float* __restrict__ bn_gamma, const float* __restrict__ bn_beta,
            const float* __restrict__ bn_mean,  const float* __restrict__ bn_var,
            float* __restrict__ out) {
    extern __shared__ char smem[];
    uint32_t sbase = smem_u32(smem);
    int b   = blockIdx.z;
    int cog = blockIdx.y;
    int pxg = blockIdx.x;
    int tid = threadIdx.x;
    int wid = tid >> 5;
    int lane = tid & 31;
    int warp_m = wid >> 2;          // 0..1 -> 64 co
    int warp_n = wid & 3;           // 0..3 -> 64 px

    float acc[4][8][4];
    #pragma unroll
    for (int i = 0; i < 4; i++)
        #pragma unroll
        for (int j = 0; j < 8; j++)
            #pragma unroll
            for (int r = 0; r < 4; r++) acc[i][j][r] = 0.f;

    // ldmatrix lane address components
    int lA_row = lane & 15;
    int lA_k16 = lane >> 4;                         // 0/1 -> +16B (k half)
    int lB_row = (lane & 7) + ((lane >> 4) & 1) * 8;  // n within 16
    int lB_k16 = (lane >> 3) & 1;

    stage_tiles(sbase, b, cog, pxg, 0, tid); CP_COMMIT();
    stage_tiles(sbase, b, cog, pxg, 1, tid); CP_COMMIT();

    for (int s = 0; s < NSTAGE; s++) {
        if (s + 1 < NSTAGE) asm volatile("cp.async.wait_group 1;" ::: "memory");
        else                asm volatile("cp.async.wait_group 0;" ::: "memory");
        __syncthreads();

        uint32_t buf = sbase + 1024 + (uint32_t)(s & 1) * BUF_BYTES;
        uint32_t Ah = buf, Al = buf + 16384, Bh = buf + 32768, Bl = buf + 65536;

        #pragma unroll
        for (int kf = 0; kf < 4; kf++) {
            uint32_t ah[16], a2[16], bb[16];
            uint32_t offA[4], offB[4];
            #pragma unroll
            for (int mi = 0; mi < 4; mi++) {
                offA[mi] = SWZ128((uint32_t)((warp_m * 64 + mi * 16 + lA_row) * 128
                                             + kf * 32 + lA_k16 * 16));
                LDSM_X4(&ah[mi * 4], Ah + offA[mi]);
            }
            #pragma unroll
            for (int j = 0; j < 4; j++) {
                offB[j] = SWZ128((uint32_t)((warp_n * 64 + j * 16 + lB_row) * 128
                                            + kf * 32 + lB_k16 * 16));
                LDSM_X4(&bb[j * 4], Bh + offB[j]);
            }
            // pass 1: Ah * Bh
            #pragma unroll
            for (int mi = 0; mi < 4; mi++)
                #pragma unroll
                for (int ni = 0; ni < 8; ni++)
                    MMA_BF16(acc[mi][ni], &ah[mi * 4],
                             bb[(ni >> 1) * 4 + (ni & 1) * 2], bb[(ni >> 1) * 4 + (ni & 1) * 2 + 1]);
            // pass 2: Al * Bh
            #pragma unroll
            for (int mi = 0; mi < 4; mi++) LDSM_X4(&a2[mi * 4], Al + offA[mi]);
            #pragma unroll
            for (int mi = 0; mi < 4; mi++)
                #pragma unroll
                for (int ni = 0; ni < 8; ni++)
                    MMA_BF16(acc[mi][ni], &a2[mi * 4],
                             bb[(ni >> 1) * 4 + (ni & 1) * 2], bb[(ni >> 1) * 4 + (ni & 1) * 2 + 1]);
            // pass 3: Ah * Bl  (Bl reuses bb registers)
            #pragma unroll
            for (int j = 0; j < 4; j++) LDSM_X4(&bb[j * 4], Bl + offB[j]);
            #pragma unroll
            for (int mi = 0; mi < 4; mi++)
                #pragma unroll
                for (int ni = 0; ni < 8; ni++)
                    MMA_BF16(acc[mi][ni], &ah[mi * 4],
                             bb[(ni >> 1) * 4 + (ni & 1) * 2], bb[(ni >> 1) * 4 + (ni & 1) * 2 + 1]);
        }

        __syncthreads();
        if (s + 2 < NSTAGE) { stage_tiles(sbase, b, cog, pxg, s + 2, tid); CP_COMMIT(); }
    }

    // ---------------- epilogue: BN + ReLU + store ----------------
    int co0 = cog * 128 + warp_m * 64;
    float sc[8], sb[8];
    #pragma unroll
    for (int mi = 0; mi < 4; mi++)
        #pragma unroll
        for (int h = 0; h < 2; h++) {
            int co = co0 + mi * 16 + (lane >> 2) + h * 8;
            float s = bn_gamma[co] * rsqrtf(bn_var[co] + BN_EPS_);
            sc[mi * 2 + h] = s;
            sb[mi * 2 + h] = bn_beta[co] - bn_mean[co] * s;
        }

    int pxbase = pxg * 256 + warp_n * 64 + (lane & 3) * 2;
    #pragma unroll
    for (int mi = 0; mi < 4; mi++)
        #pragma unroll
        for (int h = 0; h < 2; h++) {
            int co = co0 + mi * 16 + (lane >> 2) + h * 8;
            float s = sc[mi * 2 + h], bbn = sb[mi * 2 + h];
            float* op = out + ((size_t)(b * COUT_ + co)) * (HW_ * HW_);
            #pragma unroll
            for (int ni = 0; ni < 8; ni++) {
                float2 v;
                v.x = fmaxf(acc[mi][ni][h * 2 + 0] * s + bbn, 0.f);
                v.y = fmaxf(acc[mi][ni][h * 2 + 1] * s + bbn, 0.f);
                *(float2*)(op + pxbase + ni * 8) = v;
            }
        }
}

// ---------------- launcher ----------------
extern "C" void kernel_launch(void* const* d_in, const int* in_sizes, int n_in,
                              void* d_out, int out_size) {
    const float* x        = (const float*)d_in[0];
    const float* weight   = (const float*)d_in[1];
    const float* w_lambda = (const float*)d_in[2];
    const float* w_theta  = (const float*)d_in[3];
    const float* bn_gamma = (const float*)d_in[4];
    const float* bn_beta  = (const float*)d_in[5];
    const float* bn_mean  = (const float*)d_in[6];
    const float* bn_var   = (const float*)d_in[7];
    float* out = (float*)d_out;

    cudaFuncSetAttribute(conv_kernel, cudaFuncAttributeMaxDynamicSharedMemorySize,
                         1024 + 2 * BUF_BYTES);

    pool_kernel<<<B_ * CIN_, 256>>>(x);
    route_kernel<<<1, 64>>>(w_lambda, w_theta);
    rotw_kernel<<<dim3(COUT_, B_), 256>>>(weight);
    border_kernel<<<dim3(PROWS, B_), 128>>>();
    xpose_kernel<<<dim3(128, 4, B_), 256>>>(x);
    conv_kernel<<<dim3(16, 2, B_), 256, 1024 + 2 * BUF_BYTES>>>(
        bn_gamma, bn_beta, bn_mean, bn_var, out);
}